// round 9
// baseline (speedup 1.0000x reference)
#include <cuda_runtime.h>
#include <cuda_bf16.h>
#include <cuda_fp16.h>
#include <cstdint>

// Problem constants
#define NN      50000        // nodes
#define EE      800000       // edges
#define MM      (EE + NN)    // edges + self loops
#define HH      8            // heads
#define RP1     9            // relations + 1 (self-loop relation = 8)
#define NEG_SLOPE 0.2f

#define NB      80           // GEMM N: 64 hidden dims + 8 s_in + 8 s_out
#define MT2     391          // ceil(NN / 128)
#define G16     3128         // 391*8 node-groups of 16
#define SB1     196          // ceil(NN / 256) scan blocks

// ---------------------------------------------------------------------------
// Scratch (device globals; allocation-free per harness rules)
// ---------------------------------------------------------------------------
__device__ __half         g_hidden[(size_t)RP1 * NN * 64]; // 57.6 MB fp16
__device__ __half         g_s[(size_t)RP1 * NN * 16];      // 14.4 MB fp16
__device__ __nv_bfloat16  g_B[RP1 * NB * 128];             // B' hi|lo rows (K=128)
__device__ uint4          g_xa[(size_t)G16 * 8 * 32];      // A in MMA-frag order
__device__ uint4          g_Bf[RP1 * 1280];                // B in MMA-frag order
// CSR sort scratch
__device__ int            g_cnt[NN];
__device__ int            g_cnt2[NN];
__device__ int            g_off[NN + 1];
__device__ int            g_bsum[256];
__device__ uint2          g_erec[MM];                      // (ni | rel<<16, ew)

// ---------------------------------------------------------------------------
__device__ __forceinline__ void mma_bf16(float* c, uint32_t a0, uint32_t a1,
                                         uint32_t a2, uint32_t a3,
                                         uint32_t b0, uint32_t b1) {
    asm volatile(
        "mma.sync.aligned.m16n8k16.row.col.f32.bf16.bf16.f32 "
        "{%0,%1,%2,%3}, {%4,%5,%6,%7}, {%8,%9}, {%0,%1,%2,%3};"
        : "+f"(c[0]), "+f"(c[1]), "+f"(c[2]), "+f"(c[3])
        : "r"(a0), "r"(a1), "r"(a2), "r"(a3), "r"(b0), "r"(b1));
}
__device__ __forceinline__ uint32_t pack_bf2(float a, float b) {
    __nv_bfloat162 p = __halves2bfloat162(__float2bfloat16(a), __float2bfloat16(b));
    return *(uint32_t*)&p;
}
__device__ __forceinline__ float resid(float v) {
    return v - __bfloat162float(__float2bfloat16(v));
}
__device__ __forceinline__ uint32_t pack_h2(float a, float b) {
    __half2 p = __floats2half2_rn(a, b);
    return *(uint32_t*)&p;
}

// ---------------------------------------------------------------------------
// K0: zero sort counters
// ---------------------------------------------------------------------------
__global__ void k_zero() {
    int i = blockIdx.x * 256 + threadIdx.x;
    if (i < NN) { g_cnt[i] = 0; g_cnt2[i] = 0; }
}

// ---------------------------------------------------------------------------
// KpX: write x directly in m16n8k16 A-fragment order, bf16 hi|lo (K=128).
// ---------------------------------------------------------------------------
__global__ void k_prepX(const float* __restrict__ x) {
    int i = blockIdx.x * 256 + threadIdx.x;
    if (i >= G16 * 4 * 32) return;
    const int lane = i & 31;
    const int cbb  = (i >> 5) & 3;
    const int g16  = i >> 7;
    const int g = lane >> 2, t = lane & 3;
    const int n0 = g16 * 16 + g, n1 = n0 + 8;
    const int c0 = cbb * 16 + 2 * t;

    float2 v00 = {0.f, 0.f}, v01 = {0.f, 0.f}, v10 = {0.f, 0.f}, v11 = {0.f, 0.f};
    if (n0 < NN) {
        v00 = *(const float2*)(x + (size_t)n0 * 64 + c0);
        v01 = *(const float2*)(x + (size_t)n0 * 64 + c0 + 8);
    }
    if (n1 < NN) {
        v10 = *(const float2*)(x + (size_t)n1 * 64 + c0);
        v11 = *(const float2*)(x + (size_t)n1 * 64 + c0 + 8);
    }
    uint4 hi, lo;
    hi.x = pack_bf2(v00.x, v00.y);         lo.x = pack_bf2(resid(v00.x), resid(v00.y));
    hi.y = pack_bf2(v10.x, v10.y);         lo.y = pack_bf2(resid(v10.x), resid(v10.y));
    hi.z = pack_bf2(v01.x, v01.y);         lo.z = pack_bf2(resid(v01.x), resid(v01.y));
    hi.w = pack_bf2(v11.x, v11.y);         lo.w = pack_bf2(resid(v11.x), resid(v11.y));

    g_xa[((size_t)g16 * 8 + cbb) * 32 + lane]     = hi;
    g_xa[((size_t)g16 * 8 + cbb + 4) * 32 + lane] = lo;
}

// ---------------------------------------------------------------------------
// KpWB: B' rows = [W_tau | q_even-folded | q_odd-folded], bf16 hi|lo, then
//   permute to B-fragment order in g_Bf.
// ---------------------------------------------------------------------------
__global__ void k_prepWB(const float* __restrict__ W, const float* __restrict__ query) {
    const int r = blockIdx.x, tid = threadIdx.x;
    const float* Wr = W + (size_t)r * 64 * 64;

    if (tid < NB) {
        __nv_bfloat16* b = g_B + ((size_t)r * NB + tid) * 128;
        for (int i = 0; i < 64; i++) {
            float v;
            if (tid < 64) {
                v = Wr[tid * 64 + i];
            } else {
                int h = (tid - 64) & 7;
                int par = (tid - 64) >> 3;
                const float* q = query + ((size_t)r * HH + h) * 16 + par;
                float acc = 0.f;
                #pragma unroll
                for (int j = 0; j < 8; j++) acc += q[2 * j] * Wr[(h * 8 + j) * 64 + i];
                v = acc;
            }
            __nv_bfloat16 hi = __float2bfloat16(v);
            b[i]      = hi;
            b[64 + i] = __float2bfloat16(v - __bfloat162float(hi));
        }
    }
    __syncthreads();

    #pragma unroll
    for (int k = 0; k < 5; k++) {
        int f = tid + k * 256;             // 0..1279
        int cb   = f / 160;
        int rem  = f - cb * 160;
        int j    = rem >> 5;
        int lane = rem & 31;
        int g = lane >> 2, t = lane & 3;
        const __nv_bfloat16* B0 = g_B + ((size_t)r * NB + j * 16 + g) * 128;
        const __nv_bfloat16* B1 = B0 + 8 * 128;
        uint4 v;
        v.x = *(const uint32_t*)(B0 + cb * 16 + 2 * t);
        v.y = *(const uint32_t*)(B0 + cb * 16 + 8 + 2 * t);
        v.z = *(const uint32_t*)(B1 + cb * 16 + 2 * t);
        v.w = *(const uint32_t*)(B1 + cb * 16 + 8 + 2 * t);
        g_Bf[r * 1280 + f] = v;
    }
}

// ---------------------------------------------------------------------------
// Counting sort by destination: histogram -> 2-level scan -> scatter
// ---------------------------------------------------------------------------
__global__ void k_hist(const int* __restrict__ node_out) {
    int m = blockIdx.x * 256 + threadIdx.x;
    if (m >= MM) return;
    int no = (m < EE) ? node_out[m] : (m - EE);
    atomicAdd(&g_cnt[no], 1);
}

__device__ __forceinline__ int block_incl_scan(int v, int* wt) {
    int lane = threadIdx.x & 31, w = threadIdx.x >> 5;
    #pragma unroll
    for (int o = 1; o < 32; o <<= 1) {
        int y = __shfl_up_sync(0xffffffffu, v, o);
        if (lane >= o) v += y;
    }
    if (lane == 31) wt[w] = v;
    __syncthreads();
    if (w == 0) {
        int x = (lane < 8) ? wt[lane] : 0;
        #pragma unroll
        for (int o = 1; o < 8; o <<= 1) {
            int y = __shfl_up_sync(0xffffffffu, x, o);
            if (lane >= o) x += y;
        }
        if (lane < 8) wt[lane] = x;
    }
    __syncthreads();
    return v + ((w > 0) ? wt[w - 1] : 0);
}

__global__ void k_scan1() {
    __shared__ int wt[8];
    int i = blockIdx.x * 256 + threadIdx.x;
    int v0 = (i < NN) ? g_cnt[i] : 0;
    int incl = block_incl_scan(v0, wt);
    if (i < NN) g_off[i] = incl - v0;      // block-local exclusive
    if (threadIdx.x == 255) g_bsum[blockIdx.x] = incl;
}

__global__ void k_scan2() {
    __shared__ int wt[8];
    int i = threadIdx.x;
    int v0 = (i < SB1) ? g_bsum[i] : 0;
    int incl = block_incl_scan(v0, wt);
    g_bsum[i] = incl - v0;                 // exclusive block offsets
}

__global__ void k_scan3() {
    int i = blockIdx.x * 256 + threadIdx.x;
    if (i < NN) g_off[i] += g_bsum[i >> 8];
    if (i == 0) g_off[NN] = MM;
}

__global__ void k_scatter(const int* __restrict__ node_in,
                          const int* __restrict__ node_out,
                          const int* __restrict__ relation,
                          const float* __restrict__ edge_weight) {
    int m = blockIdx.x * 256 + threadIdx.x;
    if (m >= MM) return;
    int ni, no, r; float ew;
    if (m < EE) {
        ni = node_in[m]; no = node_out[m]; r = relation[m]; ew = edge_weight[m];
    } else {
        ni = no = m - EE; r = RP1 - 1; ew = 1.f;
    }
    int pos = g_off[no] + atomicAdd(&g_cnt2[no], 1);
    g_erec[pos] = make_uint2((uint32_t)ni | ((uint32_t)r << 16), __float_as_uint(ew));
}

// ---------------------------------------------------------------------------
// Kg: mma.sync bf16 GEMM, frag-direct A. CTA = 128 nodes x 80 cols.
// ---------------------------------------------------------------------------
__global__ __launch_bounds__(128) void k_gemm(int dummy) {
    __shared__ uint4 sBf[1280];            // 20 KB

    const int r     = blockIdx.y;
    const int mbase = blockIdx.x * 128;
    const int tid   = threadIdx.x;
    const int w     = tid >> 5, lane = tid & 31;

    #pragma unroll
    for (int k = 0; k < 10; k++)
        sBf[tid + k * 128] = g_Bf[r * 1280 + tid + k * 128];

    uint4 af[2][8];
    const int gb = blockIdx.x * 8 + w * 2;
    #pragma unroll
    for (int i = 0; i < 2; i++)
        #pragma unroll
        for (int cb = 0; cb < 8; cb++)
            af[i][cb] = g_xa[((size_t)(gb + i) * 8 + cb) * 32 + lane];

    __syncthreads();

    float acc[2][40];
    #pragma unroll
    for (int i = 0; i < 2; i++)
        #pragma unroll
        for (int k = 0; k < 40; k++) acc[i][k] = 0.f;

    #pragma unroll
    for (int cb = 0; cb < 8; cb++) {
        uint4 bf[5];
        #pragma unroll
        for (int j = 0; j < 5; j++) bf[j] = sBf[(cb * 5 + j) * 32 + lane];

        const int nA = (cb < 4) ? 2 : 1;
        #pragma unroll
        for (int u = 0; u < 2; u++) {
            if (u < nA) {
                const int ca = (u == 0) ? ((cb < 4) ? cb : cb - 4) : cb + 4;
                #pragma unroll
                for (int i = 0; i < 2; i++)
                    #pragma unroll
                    for (int nt = 0; nt < 10; nt++) {
                        uint32_t b0 = (nt & 1) ? bf[nt >> 1].z : bf[nt >> 1].x;
                        uint32_t b1 = (nt & 1) ? bf[nt >> 1].w : bf[nt >> 1].y;
                        mma_bf16(acc[i] + nt * 4, af[i][ca].x, af[i][ca].y,
                                 af[i][ca].z, af[i][ca].w, b0, b1);
                    }
            }
        }
    }

    const int g = lane >> 2, t = lane & 3;
    #pragma unroll
    for (int i = 0; i < 2; i++)
        #pragma unroll
        for (int half = 0; half < 2; half++) {
            int n = mbase + w * 32 + i * 16 + g + 8 * half;
            if (n < NN) {
                uint32_t* hd = (uint32_t*)(g_hidden + ((size_t)r * NN + n) * 64 + 2 * t);
                #pragma unroll
                for (int nt = 0; nt < 8; nt++)
                    hd[nt * 4] = pack_h2(acc[i][nt * 4 + 2 * half],
                                         acc[i][nt * 4 + 2 * half + 1]);
                uint32_t* sd = (uint32_t*)(g_s + ((size_t)r * NN + n) * 16 + 2 * t);
                #pragma unroll
                for (int nt = 8; nt < 10; nt++)
                    sd[(nt - 8) * 4] = pack_h2(acc[i][nt * 4 + 2 * half],
                                               acc[i][nt * 4 + 2 * half + 1]);
            }
        }
}

// ---------------------------------------------------------------------------
// Ka: gather-side aggregation, software-pipelined depth 4.
//   One warp per destination node; lanes own dims (2l, 2l+1).
//   Chunks of 4 edges: all 4 h_in lines + 8 s-halves issue independently
//   (MLP ~12) before any accumulation. Padded slots carry ew=0 (zero
//   contribution, no branch). No atomics. Fused normalize+ReLU+store.
// ---------------------------------------------------------------------------
__global__ __launch_bounds__(256) void k_agg(float* __restrict__ out) {
    const int n = blockIdx.x * 8 + (threadIdx.x >> 5);
    if (n >= NN) return;
    const int lane = threadIdx.x & 31;
    const int h = lane >> 2;

    const int start = g_off[n];
    const int end   = g_off[n + 1];

    float acc0 = 0.f, acc1 = 0.f, esum = 0.f;

    // pad record: ni=0, r=0, ew=0 -> zero contribution, valid addresses
    const uint2 PADR = make_uint2(0u, 0u);

    uint2 rec[4];
    #pragma unroll
    for (int j = 0; j < 4; j++)
        rec[j] = (start + j < end) ? g_erec[start + j] : PADR;

    for (int e = start; e < end; e += 4) {
        uint2 cur[4];
        #pragma unroll
        for (int j = 0; j < 4; j++) cur[j] = rec[j];

        // prefetch next chunk's records
        #pragma unroll
        for (int j = 0; j < 4; j++)
            rec[j] = (e + 4 + j < end) ? g_erec[e + 4 + j] : PADR;

        // issue all data loads for this chunk (independent addresses)
        uint32_t hv[4];
        __half sin[4], sout[4];
        #pragma unroll
        for (int j = 0; j < 4; j++) {
            const int ni = (int)(cur[j].x & 0xFFFFu);
            const int r  = (int)(cur[j].x >> 16);
            const size_t bi = (size_t)r * NN + ni;
            const size_t bo = (size_t)r * NN + n;
            hv[j]   = *(const uint32_t*)(g_hidden + bi * 64 + 2 * lane);
            sin[j]  = g_s[bi * 16 + h];
            sout[j] = g_s[bo * 16 + 8 + h];
        }

        // accumulate
        #pragma unroll
        for (int j = 0; j < 4; j++) {
            float w = __half2float(sin[j]) + __half2float(sout[j]);
            w = (w > 0.f) ? w : NEG_SLOPE * w;
            const float ee = __expf(w) * __uint_as_float(cur[j].y);
            const float2 f = __half22float2(*(const __half2*)&hv[j]);
            acc0 += ee * f.x;
            acc1 += ee * f.y;
            esum += ee;
        }
    }

    const float inv = 1.f / esum;          // every node has >=1 edge (self-loop)
    float o0 = acc0 * inv, o1 = acc1 * inv;
    o0 = (o0 > 0.f) ? o0 : 0.f;
    o1 = (o1 > 0.f) ? o1 : 0.f;
    *(float2*)(out + (size_t)n * 64 + 2 * lane) = make_float2(o0, o1);
}

// ---------------------------------------------------------------------------
extern "C" void kernel_launch(void* const* d_in, const int* in_sizes, int n_in,
                              void* d_out, int out_size) {
    const float* x           = (const float*)d_in[0];
    const float* W_tau       = (const float*)d_in[1];
    const float* query       = (const float*)d_in[2];
    const int*   node_in     = (const int*)  d_in[3];
    const int*   node_out    = (const int*)  d_in[4];
    const int*   relation    = (const int*)  d_in[5];
    const float* edge_weight = (const float*)d_in[6];

    k_zero<<<(NN + 255) / 256, 256>>>();
    k_prepX<<<(G16 * 4 * 32 + 255) / 256, 256>>>(x);
    k_prepWB<<<RP1, 256>>>(W_tau, query);

    // CSR sort by destination
    k_hist<<<(MM + 255) / 256, 256>>>(node_out);
    k_scan1<<<SB1, 256>>>();
    k_scan2<<<1, 256>>>();
    k_scan3<<<SB1, 256>>>();
    k_scatter<<<(MM + 255) / 256, 256>>>(node_in, node_out, relation, edge_weight);

    // node transform (tensor cores)
    dim3 gg(MT2, RP1);
    k_gemm<<<gg, 128>>>(0);

    // gather-side aggregation, fused finalize
    k_agg<<<(NN + 7) / 8, 256>>>((float*)d_out);
}

// round 10
// speedup vs baseline: 1.1437x; 1.1437x over previous
#include <cuda_runtime.h>
#include <cuda_bf16.h>
#include <cuda_fp16.h>
#include <cstdint>

// Problem constants
#define NN      50000        // nodes
#define EE      800000       // edges
#define MM      (EE + NN)    // edges + self loops
#define HH      8            // heads
#define RP1     9            // relations + 1 (self-loop relation = 8)
#define NEG_SLOPE 0.2f

#define NB      80           // GEMM N: 64 hidden dims + 8 s_in + 8 s_out
#define MT2     391          // ceil(NN / 128)
#define G16     3128         // 391*8 node-groups of 16
#define SB1     196          // ceil(NN / 256) scan blocks

// ---------------------------------------------------------------------------
// Scratch (device globals; allocation-free per harness rules)
// ---------------------------------------------------------------------------
__device__ __half         g_hidden[(size_t)RP1 * NN * 64]; // 57.6 MB fp16
__device__ __half         g_s[(size_t)RP1 * NN * 16];      // 14.4 MB fp16
__device__ __nv_bfloat16  g_B[RP1 * NB * 128];             // B' hi|lo rows (K=128)
__device__ uint4          g_xa[(size_t)G16 * 8 * 32];      // A in MMA-frag order
__device__ uint4          g_Bf[RP1 * 1280];                // B in MMA-frag order
// CSR sort scratch
__device__ int            g_cnt[NN];
__device__ int            g_cnt2[NN];
__device__ int            g_off[NN + 1];
__device__ int            g_bsum[256];
__device__ uint2          g_erec[MM];                      // (bi | rel<<24, ew)

// ---------------------------------------------------------------------------
__device__ __forceinline__ void mma_bf16(float* c, uint32_t a0, uint32_t a1,
                                         uint32_t a2, uint32_t a3,
                                         uint32_t b0, uint32_t b1) {
    asm volatile(
        "mma.sync.aligned.m16n8k16.row.col.f32.bf16.bf16.f32 "
        "{%0,%1,%2,%3}, {%4,%5,%6,%7}, {%8,%9}, {%0,%1,%2,%3};"
        : "+f"(c[0]), "+f"(c[1]), "+f"(c[2]), "+f"(c[3])
        : "r"(a0), "r"(a1), "r"(a2), "r"(a3), "r"(b0), "r"(b1));
}
__device__ __forceinline__ uint32_t pack_bf2(float a, float b) {
    __nv_bfloat162 p = __halves2bfloat162(__float2bfloat16(a), __float2bfloat16(b));
    return *(uint32_t*)&p;
}
__device__ __forceinline__ float resid(float v) {
    return v - __bfloat162float(__float2bfloat16(v));
}
__device__ __forceinline__ uint32_t pack_h2(float a, float b) {
    __half2 p = __floats2half2_rn(a, b);
    return *(uint32_t*)&p;
}

// ---------------------------------------------------------------------------
// K0: zero sort counters
// ---------------------------------------------------------------------------
__global__ void k_zero() {
    int i = blockIdx.x * 256 + threadIdx.x;
    if (i < NN) { g_cnt[i] = 0; g_cnt2[i] = 0; }
}

// ---------------------------------------------------------------------------
// KpX: write x directly in m16n8k16 A-fragment order, bf16 hi|lo (K=128).
// ---------------------------------------------------------------------------
__global__ void k_prepX(const float* __restrict__ x) {
    int i = blockIdx.x * 256 + threadIdx.x;
    if (i >= G16 * 4 * 32) return;
    const int lane = i & 31;
    const int cbb  = (i >> 5) & 3;
    const int g16  = i >> 7;
    const int g = lane >> 2, t = lane & 3;
    const int n0 = g16 * 16 + g, n1 = n0 + 8;
    const int c0 = cbb * 16 + 2 * t;

    float2 v00 = {0.f, 0.f}, v01 = {0.f, 0.f}, v10 = {0.f, 0.f}, v11 = {0.f, 0.f};
    if (n0 < NN) {
        v00 = *(const float2*)(x + (size_t)n0 * 64 + c0);
        v01 = *(const float2*)(x + (size_t)n0 * 64 + c0 + 8);
    }
    if (n1 < NN) {
        v10 = *(const float2*)(x + (size_t)n1 * 64 + c0);
        v11 = *(const float2*)(x + (size_t)n1 * 64 + c0 + 8);
    }
    uint4 hi, lo;
    hi.x = pack_bf2(v00.x, v00.y);         lo.x = pack_bf2(resid(v00.x), resid(v00.y));
    hi.y = pack_bf2(v10.x, v10.y);         lo.y = pack_bf2(resid(v10.x), resid(v10.y));
    hi.z = pack_bf2(v01.x, v01.y);         lo.z = pack_bf2(resid(v01.x), resid(v01.y));
    hi.w = pack_bf2(v11.x, v11.y);         lo.w = pack_bf2(resid(v11.x), resid(v11.y));

    g_xa[((size_t)g16 * 8 + cbb) * 32 + lane]     = hi;
    g_xa[((size_t)g16 * 8 + cbb + 4) * 32 + lane] = lo;
}

// ---------------------------------------------------------------------------
// KpWB: B' rows = [W_tau | q_even-folded | q_odd-folded], bf16 hi|lo, then
//   permute to B-fragment order in g_Bf.
// ---------------------------------------------------------------------------
__global__ void k_prepWB(const float* __restrict__ W, const float* __restrict__ query) {
    const int r = blockIdx.x, tid = threadIdx.x;
    const float* Wr = W + (size_t)r * 64 * 64;

    if (tid < NB) {
        __nv_bfloat16* b = g_B + ((size_t)r * NB + tid) * 128;
        for (int i = 0; i < 64; i++) {
            float v;
            if (tid < 64) {
                v = Wr[tid * 64 + i];
            } else {
                int h = (tid - 64) & 7;
                int par = (tid - 64) >> 3;
                const float* q = query + ((size_t)r * HH + h) * 16 + par;
                float acc = 0.f;
                #pragma unroll
                for (int j = 0; j < 8; j++) acc += q[2 * j] * Wr[(h * 8 + j) * 64 + i];
                v = acc;
            }
            __nv_bfloat16 hi = __float2bfloat16(v);
            b[i]      = hi;
            b[64 + i] = __float2bfloat16(v - __bfloat162float(hi));
        }
    }
    __syncthreads();

    #pragma unroll
    for (int k = 0; k < 5; k++) {
        int f = tid + k * 256;             // 0..1279
        int cb   = f / 160;
        int rem  = f - cb * 160;
        int j    = rem >> 5;
        int lane = rem & 31;
        int g = lane >> 2, t = lane & 3;
        const __nv_bfloat16* B0 = g_B + ((size_t)r * NB + j * 16 + g) * 128;
        const __nv_bfloat16* B1 = B0 + 8 * 128;
        uint4 v;
        v.x = *(const uint32_t*)(B0 + cb * 16 + 2 * t);
        v.y = *(const uint32_t*)(B0 + cb * 16 + 8 + 2 * t);
        v.z = *(const uint32_t*)(B1 + cb * 16 + 2 * t);
        v.w = *(const uint32_t*)(B1 + cb * 16 + 8 + 2 * t);
        g_Bf[r * 1280 + f] = v;
    }
}

// ---------------------------------------------------------------------------
// Kg: mma.sync bf16 GEMM, frag-direct A, TWO relations per CTA
//   (A fragments loaded once, reused across both relations).
// ---------------------------------------------------------------------------
__global__ __launch_bounds__(128) void k_gemm(int dummy) {
    __shared__ uint4 sBf[2][1280];         // 40 KB

    const int r0    = blockIdx.y * 2;
    const int nrel  = (r0 + 1 < RP1) ? 2 : 1;
    const int mbase = blockIdx.x * 128;
    const int tid   = threadIdx.x;
    const int w     = tid >> 5, lane = tid & 31;

    for (int p = 0; p < nrel; p++)
        #pragma unroll
        for (int k = 0; k < 10; k++)
            sBf[p][tid + k * 128] = g_Bf[(r0 + p) * 1280 + tid + k * 128];

    uint4 af[2][8];
    const int gb = blockIdx.x * 8 + w * 2;
    #pragma unroll
    for (int i = 0; i < 2; i++)
        #pragma unroll
        for (int cb = 0; cb < 8; cb++)
            af[i][cb] = g_xa[((size_t)(gb + i) * 8 + cb) * 32 + lane];

    __syncthreads();

    const int g = lane >> 2, t = lane & 3;

    for (int p = 0; p < nrel; p++) {
        const int r = r0 + p;

        float acc[2][40];
        #pragma unroll
        for (int i = 0; i < 2; i++)
            #pragma unroll
            for (int k = 0; k < 40; k++) acc[i][k] = 0.f;

        #pragma unroll
        for (int cb = 0; cb < 8; cb++) {
            uint4 bf[5];
            #pragma unroll
            for (int j = 0; j < 5; j++) bf[j] = sBf[p][(cb * 5 + j) * 32 + lane];

            const int nA = (cb < 4) ? 2 : 1;
            #pragma unroll
            for (int u = 0; u < 2; u++) {
                if (u < nA) {
                    const int ca = (u == 0) ? ((cb < 4) ? cb : cb - 4) : cb + 4;
                    #pragma unroll
                    for (int i = 0; i < 2; i++)
                        #pragma unroll
                        for (int nt = 0; nt < 10; nt++) {
                            uint32_t b0 = (nt & 1) ? bf[nt >> 1].z : bf[nt >> 1].x;
                            uint32_t b1 = (nt & 1) ? bf[nt >> 1].w : bf[nt >> 1].y;
                            mma_bf16(acc[i] + nt * 4, af[i][ca].x, af[i][ca].y,
                                     af[i][ca].z, af[i][ca].w, b0, b1);
                        }
                }
            }
        }

        #pragma unroll
        for (int i = 0; i < 2; i++)
            #pragma unroll
            for (int half = 0; half < 2; half++) {
                int n = mbase + w * 32 + i * 16 + g + 8 * half;
                if (n < NN) {
                    uint32_t* hd = (uint32_t*)(g_hidden + ((size_t)r * NN + n) * 64 + 2 * t);
                    #pragma unroll
                    for (int nt = 0; nt < 8; nt++)
                        hd[nt * 4] = pack_h2(acc[i][nt * 4 + 2 * half],
                                             acc[i][nt * 4 + 2 * half + 1]);
                    uint32_t* sd = (uint32_t*)(g_s + ((size_t)r * NN + n) * 16 + 2 * t);
                    #pragma unroll
                    for (int nt = 8; nt < 10; nt++)
                        sd[(nt - 8) * 4] = pack_h2(acc[i][nt * 4 + 2 * half],
                                                   acc[i][nt * 4 + 2 * half + 1]);
                }
            }
    }
}

// ---------------------------------------------------------------------------
// Counting sort by destination: histogram -> 2-level scan -> scatter
// ---------------------------------------------------------------------------
__global__ void k_hist(const int* __restrict__ node_out) {
    int m = blockIdx.x * 256 + threadIdx.x;
    if (m >= MM) return;
    int no = (m < EE) ? node_out[m] : (m - EE);
    atomicAdd(&g_cnt[no], 1);
}

__device__ __forceinline__ int block_incl_scan(int v, int* wt) {
    int lane = threadIdx.x & 31, w = threadIdx.x >> 5;
    #pragma unroll
    for (int o = 1; o < 32; o <<= 1) {
        int y = __shfl_up_sync(0xffffffffu, v, o);
        if (lane >= o) v += y;
    }
    if (lane == 31) wt[w] = v;
    __syncthreads();
    if (w == 0) {
        int x = (lane < 8) ? wt[lane] : 0;
        #pragma unroll
        for (int o = 1; o < 8; o <<= 1) {
            int y = __shfl_up_sync(0xffffffffu, x, o);
            if (lane >= o) x += y;
        }
        if (lane < 8) wt[lane] = x;
    }
    __syncthreads();
    return v + ((w > 0) ? wt[w - 1] : 0);
}

__global__ void k_scan1() {
    __shared__ int wt[8];
    int i = blockIdx.x * 256 + threadIdx.x;
    int v0 = (i < NN) ? g_cnt[i] : 0;
    int incl = block_incl_scan(v0, wt);
    if (i < NN) g_off[i] = incl - v0;      // block-local exclusive
    if (threadIdx.x == 255) g_bsum[blockIdx.x] = incl;
}

__global__ void k_scan2() {
    __shared__ int wt[8];
    int i = threadIdx.x;
    int v0 = (i < SB1) ? g_bsum[i] : 0;
    int incl = block_incl_scan(v0, wt);
    g_bsum[i] = incl - v0;                 // exclusive block offsets
}

__global__ void k_scan3() {
    int i = blockIdx.x * 256 + threadIdx.x;
    if (i < NN) g_off[i] += g_bsum[i >> 8];
    if (i == 0) g_off[NN] = MM;
}

__global__ void k_scatter(const int* __restrict__ node_in,
                          const int* __restrict__ node_out,
                          const int* __restrict__ relation,
                          const float* __restrict__ edge_weight) {
    int m = blockIdx.x * 256 + threadIdx.x;
    if (m >= MM) return;
    int ni, no, r; float ew;
    if (m < EE) {
        ni = node_in[m]; no = node_out[m]; r = relation[m]; ew = edge_weight[m];
    } else {
        ni = no = m - EE; r = RP1 - 1; ew = 1.f;
    }
    int pos = g_off[no] + atomicAdd(&g_cnt2[no], 1);
    uint32_t bi = (uint32_t)r * NN + (uint32_t)ni;   // < 450000, fits 19 bits
    g_erec[pos] = make_uint2(bi | ((uint32_t)r << 24), __float_as_uint(ew));
}

// ---------------------------------------------------------------------------
// Ka: gather-side aggregation, 4 edges per warp-step.
//   lane = jj*8 + dd: jj = edge slot (0..3), dd = head / dim-octet (0..7).
//   Per step: 1 uint4 LDG covers 4 h_in lines; 1 half each for s_in/s_out
//   per (edge,head) — no redundant logit math. 8 fp32 acc per lane; final
//   butterfly (xor 8,16) folds edge slots. No atomics.
// ---------------------------------------------------------------------------
__global__ __launch_bounds__(256) void k_agg(float* __restrict__ out) {
    const int n = blockIdx.x * 8 + (threadIdx.x >> 5);
    if (n >= NN) return;
    const int lane = threadIdx.x & 31;
    const int jj = lane >> 3, dd = lane & 7;

    const int start = g_off[n];
    const int end   = g_off[n + 1];

    float acc[8];
    #pragma unroll
    for (int k = 0; k < 8; k++) acc[k] = 0.f;
    float esum = 0.f;

    for (int e = start; e < end; e += 4) {
        const int idx = e + jj;
        // pad record (bi=0, r=0, ew=0) -> zero contribution, valid addresses
        uint2 cur = (idx < end) ? g_erec[idx] : make_uint2(0u, 0u);
        const uint32_t bi = cur.x & 0xFFFFFFu;
        const uint32_t r  = cur.x >> 24;

        const uint4 hv = *(const uint4*)(g_hidden + (size_t)bi * 64 + dd * 8);
        const float si = __half2float(g_s[(size_t)bi * 16 + dd]);
        const float so = __half2float(g_s[((size_t)r * NN + n) * 16 + 8 + dd]);

        float w = si + so;
        w = (w > 0.f) ? w : NEG_SLOPE * w;
        const float ee = __expf(w) * __uint_as_float(cur.y);

        const float2 f0 = __half22float2(*(const __half2*)&hv.x);
        const float2 f1 = __half22float2(*(const __half2*)&hv.y);
        const float2 f2 = __half22float2(*(const __half2*)&hv.z);
        const float2 f3 = __half22float2(*(const __half2*)&hv.w);
        acc[0] += ee * f0.x; acc[1] += ee * f0.y;
        acc[2] += ee * f1.x; acc[3] += ee * f1.y;
        acc[4] += ee * f2.x; acc[5] += ee * f2.y;
        acc[6] += ee * f3.x; acc[7] += ee * f3.y;
        esum += ee;
    }

    // fold the 4 edge slots (lanes jj, same dd)
    #pragma unroll
    for (int o = 8; o <= 16; o <<= 1) {
        #pragma unroll
        for (int k = 0; k < 8; k++)
            acc[k] += __shfl_xor_sync(0xffffffffu, acc[k], o);
        esum += __shfl_xor_sync(0xffffffffu, esum, o);
    }

    if (jj == 0) {
        const float inv = 1.f / esum;      // >=1 edge per node (self-loop)
        float4 o0, o1;
        o0.x = fmaxf(acc[0] * inv, 0.f);
        o0.y = fmaxf(acc[1] * inv, 0.f);
        o0.z = fmaxf(acc[2] * inv, 0.f);
        o0.w = fmaxf(acc[3] * inv, 0.f);
        o1.x = fmaxf(acc[4] * inv, 0.f);
        o1.y = fmaxf(acc[5] * inv, 0.f);
        o1.z = fmaxf(acc[6] * inv, 0.f);
        o1.w = fmaxf(acc[7] * inv, 0.f);
        *(float4*)(out + (size_t)n * 64 + dd * 8)     = o0;
        *(float4*)(out + (size_t)n * 64 + dd * 8 + 4) = o1;
    }
}

// ---------------------------------------------------------------------------
extern "C" void kernel_launch(void* const* d_in, const int* in_sizes, int n_in,
                              void* d_out, int out_size) {
    const float* x           = (const float*)d_in[0];
    const float* W_tau       = (const float*)d_in[1];
    const float* query       = (const float*)d_in[2];
    const int*   node_in     = (const int*)  d_in[3];
    const int*   node_out    = (const int*)  d_in[4];
    const int*   relation    = (const int*)  d_in[5];
    const float* edge_weight = (const float*)d_in[6];

    k_zero<<<(NN + 255) / 256, 256>>>();
    k_prepX<<<(G16 * 4 * 32 + 255) / 256, 256>>>(x);
    k_prepWB<<<RP1, 256>>>(W_tau, query);

    // node transform (tensor cores) — 4th launch: captured by ncu
    dim3 gg(MT2, 5);
    k_gemm<<<gg, 128>>>(0);

    // CSR sort by destination
    k_hist<<<(MM + 255) / 256, 256>>>(node_out);
    k_scan1<<<SB1, 256>>>();
    k_scan2<<<1, 256>>>();
    k_scan3<<<SB1, 256>>>();
    k_scatter<<<(MM + 255) / 256, 256>>>(node_in, node_out, relation, edge_weight);

    // gather-side aggregation, fused finalize
    k_agg<<<(NN + 7) / 8, 256>>>((float*)d_out);
}

// round 11
// speedup vs baseline: 1.3412x; 1.1727x over previous
#include <cuda_runtime.h>
#include <cuda_bf16.h>
#include <cuda_fp16.h>
#include <cstdint>

// Problem constants
#define NN      50000        // nodes
#define EE      800000       // edges
#define MM      (EE + NN)    // edges + self loops
#define HH      8            // heads
#define RP1     9            // relations + 1 (self-loop relation = 8)
#define NEG_SLOPE 0.2f

#define NB      80           // GEMM N: 64 hidden dims + 8 s_in + 8 s_out
#define MT2     391          // ceil(NN / 128)
#define G16     3128         // 391*8 node-groups of 16
#define SB1     196          // ceil(NN / 256) scan blocks

// ---------------------------------------------------------------------------
// Scratch (device globals; allocation-free per harness rules)
// ---------------------------------------------------------------------------
__device__ __half         g_hidden[(size_t)RP1 * NN * 64]; // 57.6 MB fp16
__device__ __half         g_s[(size_t)RP1 * NN * 16];      // 14.4 MB fp16
__device__ __half         g_Bh[RP1 * NB * 64];             // B' rows fp16 (K=64)
__device__ uint4          g_xf[(size_t)G16 * 4 * 32];      // A fp16 frag order
__device__ uint4          g_Bf[RP1 * 640];                 // B fp16 frag order
// CSR sort scratch
__device__ int            g_cnt[NN];
__device__ int            g_cnt2[NN];
__device__ int            g_off[NN + 1];
__device__ int            g_bsum[256];
__device__ uint2          g_erec[MM];                      // (bi | rel<<24, ew)

// ---------------------------------------------------------------------------
__device__ __forceinline__ void mma_f16(float* c, uint32_t a0, uint32_t a1,
                                        uint32_t a2, uint32_t a3,
                                        uint32_t b0, uint32_t b1) {
    asm volatile(
        "mma.sync.aligned.m16n8k16.row.col.f32.f16.f16.f32 "
        "{%0,%1,%2,%3}, {%4,%5,%6,%7}, {%8,%9}, {%0,%1,%2,%3};"
        : "+f"(c[0]), "+f"(c[1]), "+f"(c[2]), "+f"(c[3])
        : "r"(a0), "r"(a1), "r"(a2), "r"(a3), "r"(b0), "r"(b1));
}
__device__ __forceinline__ uint32_t pack_h2(float a, float b) {
    __half2 p = __floats2half2_rn(a, b);
    return *(uint32_t*)&p;
}

// ---------------------------------------------------------------------------
// K0: zero sort counters
// ---------------------------------------------------------------------------
__global__ void k_zero() {
    int i = blockIdx.x * 256 + threadIdx.x;
    if (i < NN) { g_cnt[i] = 0; g_cnt2[i] = 0; }
}

// ---------------------------------------------------------------------------
// KpX: write x directly in m16n8k16 A-fragment order, fp16, K=64.
//   g_xf[g16][cb][lane] = uint4(a0,a1,a2,a3) for mtile g16, k16-chunk cb.
// ---------------------------------------------------------------------------
__global__ void k_prepX(const float* __restrict__ x) {
    int i = blockIdx.x * 256 + threadIdx.x;
    if (i >= G16 * 4 * 32) return;
    const int lane = i & 31;
    const int cbb  = (i >> 5) & 3;
    const int g16  = i >> 7;
    const int g = lane >> 2, t = lane & 3;
    const int n0 = g16 * 16 + g, n1 = n0 + 8;
    const int c0 = cbb * 16 + 2 * t;

    float2 v00 = {0.f, 0.f}, v01 = {0.f, 0.f}, v10 = {0.f, 0.f}, v11 = {0.f, 0.f};
    if (n0 < NN) {
        v00 = *(const float2*)(x + (size_t)n0 * 64 + c0);
        v01 = *(const float2*)(x + (size_t)n0 * 64 + c0 + 8);
    }
    if (n1 < NN) {
        v10 = *(const float2*)(x + (size_t)n1 * 64 + c0);
        v11 = *(const float2*)(x + (size_t)n1 * 64 + c0 + 8);
    }
    uint4 a;
    a.x = pack_h2(v00.x, v00.y);
    a.y = pack_h2(v10.x, v10.y);
    a.z = pack_h2(v01.x, v01.y);
    a.w = pack_h2(v11.x, v11.y);
    g_xf[((size_t)g16 * 4 + cbb) * 32 + lane] = a;
}

// ---------------------------------------------------------------------------
// KpWB: B' rows = [W_tau | q_even-folded | q_odd-folded] fp16 (K=64), then
//   permute to B-fragment order in g_Bf.
// ---------------------------------------------------------------------------
__global__ void k_prepWB(const float* __restrict__ W, const float* __restrict__ query) {
    const int r = blockIdx.x, tid = threadIdx.x;
    const float* Wr = W + (size_t)r * 64 * 64;

    if (tid < NB) {
        __half* b = g_Bh + ((size_t)r * NB + tid) * 64;
        for (int i = 0; i < 64; i++) {
            float v;
            if (tid < 64) {
                v = Wr[tid * 64 + i];
            } else {
                int h = (tid - 64) & 7;
                int par = (tid - 64) >> 3;
                const float* q = query + ((size_t)r * HH + h) * 16 + par;
                float acc = 0.f;
                #pragma unroll
                for (int j = 0; j < 8; j++) acc += q[2 * j] * Wr[(h * 8 + j) * 64 + i];
                v = acc;
            }
            b[i] = __float2half(v);
        }
    }
    __syncthreads();

    #pragma unroll
    for (int k = 0; k < 3; k++) {
        int f = tid + k * 256;             // 0..639
        if (f < 640) {
            int cb   = f / 160;
            int rem  = f - cb * 160;
            int j    = rem >> 5;
            int lane = rem & 31;
            int g = lane >> 2, t = lane & 3;
            const __half* B0 = g_Bh + ((size_t)r * NB + j * 16 + g) * 64;
            const __half* B1 = B0 + 8 * 64;
            uint4 v;
            v.x = *(const uint32_t*)(B0 + cb * 16 + 2 * t);
            v.y = *(const uint32_t*)(B0 + cb * 16 + 8 + 2 * t);
            v.z = *(const uint32_t*)(B1 + cb * 16 + 2 * t);
            v.w = *(const uint32_t*)(B1 + cb * 16 + 8 + 2 * t);
            g_Bf[r * 640 + f] = v;
        }
    }
}

// ---------------------------------------------------------------------------
// Kg: mma.sync fp16 GEMM, single pass K=64, frag-direct A, 2 relations/CTA.
//   80 MMAs per relation per warp (4 cb x 2 i x 10 nt).
// ---------------------------------------------------------------------------
__global__ __launch_bounds__(128) void k_gemm(int dummy) {
    __shared__ uint4 sBf[2][640];          // 20 KB

    const int r0    = blockIdx.y * 2;
    const int nrel  = (r0 + 1 < RP1) ? 2 : 1;
    const int mbase = blockIdx.x * 128;
    const int tid   = threadIdx.x;
    const int w     = tid >> 5, lane = tid & 31;

    for (int p = 0; p < nrel; p++)
        #pragma unroll
        for (int k = 0; k < 5; k++)
            sBf[p][tid + k * 128] = g_Bf[(r0 + p) * 640 + tid + k * 128];

    uint4 af[2][4];
    const int gb = blockIdx.x * 8 + w * 2;
    #pragma unroll
    for (int i = 0; i < 2; i++)
        #pragma unroll
        for (int cb = 0; cb < 4; cb++)
            af[i][cb] = g_xf[((size_t)(gb + i) * 4 + cb) * 32 + lane];

    __syncthreads();

    const int g = lane >> 2, t = lane & 3;

    for (int p = 0; p < nrel; p++) {
        const int r = r0 + p;

        float acc[2][40];
        #pragma unroll
        for (int i = 0; i < 2; i++)
            #pragma unroll
            for (int k = 0; k < 40; k++) acc[i][k] = 0.f;

        #pragma unroll
        for (int cb = 0; cb < 4; cb++) {
            uint4 bf[5];
            #pragma unroll
            for (int j = 0; j < 5; j++) bf[j] = sBf[p][(cb * 5 + j) * 32 + lane];

            #pragma unroll
            for (int i = 0; i < 2; i++)
                #pragma unroll
                for (int nt = 0; nt < 10; nt++) {
                    uint32_t b0 = (nt & 1) ? bf[nt >> 1].z : bf[nt >> 1].x;
                    uint32_t b1 = (nt & 1) ? bf[nt >> 1].w : bf[nt >> 1].y;
                    mma_f16(acc[i] + nt * 4, af[i][cb].x, af[i][cb].y,
                            af[i][cb].z, af[i][cb].w, b0, b1);
                }
        }

        #pragma unroll
        for (int i = 0; i < 2; i++)
            #pragma unroll
            for (int half = 0; half < 2; half++) {
                int n = mbase + w * 32 + i * 16 + g + 8 * half;
                if (n < NN) {
                    uint32_t* hd = (uint32_t*)(g_hidden + ((size_t)r * NN + n) * 64 + 2 * t);
                    #pragma unroll
                    for (int nt = 0; nt < 8; nt++)
                        hd[nt * 4] = pack_h2(acc[i][nt * 4 + 2 * half],
                                             acc[i][nt * 4 + 2 * half + 1]);
                    uint32_t* sd = (uint32_t*)(g_s + ((size_t)r * NN + n) * 16 + 2 * t);
                    #pragma unroll
                    for (int nt = 8; nt < 10; nt++)
                        sd[(nt - 8) * 4] = pack_h2(acc[i][nt * 4 + 2 * half],
                                                   acc[i][nt * 4 + 2 * half + 1]);
                }
            }
    }
}

// ---------------------------------------------------------------------------
// Counting sort by destination: histogram -> 2-level scan -> scatter
// ---------------------------------------------------------------------------
__global__ void k_hist(const int* __restrict__ node_out) {
    int m = blockIdx.x * 256 + threadIdx.x;
    if (m >= MM) return;
    int no = (m < EE) ? node_out[m] : (m - EE);
    atomicAdd(&g_cnt[no], 1);
}

__device__ __forceinline__ int block_incl_scan(int v, int* wt) {
    int lane = threadIdx.x & 31, w = threadIdx.x >> 5;
    #pragma unroll
    for (int o = 1; o < 32; o <<= 1) {
        int y = __shfl_up_sync(0xffffffffu, v, o);
        if (lane >= o) v += y;
    }
    if (lane == 31) wt[w] = v;
    __syncthreads();
    if (w == 0) {
        int x = (lane < 8) ? wt[lane] : 0;
        #pragma unroll
        for (int o = 1; o < 8; o <<= 1) {
            int y = __shfl_up_sync(0xffffffffu, x, o);
            if (lane >= o) x += y;
        }
        if (lane < 8) wt[lane] = x;
    }
    __syncthreads();
    return v + ((w > 0) ? wt[w - 1] : 0);
}

__global__ void k_scan1() {
    __shared__ int wt[8];
    int i = blockIdx.x * 256 + threadIdx.x;
    int v0 = (i < NN) ? g_cnt[i] : 0;
    int incl = block_incl_scan(v0, wt);
    if (i < NN) g_off[i] = incl - v0;      // block-local exclusive
    if (threadIdx.x == 255) g_bsum[blockIdx.x] = incl;
}

__global__ void k_scan2() {
    __shared__ int wt[8];
    int i = threadIdx.x;
    int v0 = (i < SB1) ? g_bsum[i] : 0;
    int incl = block_incl_scan(v0, wt);
    g_bsum[i] = incl - v0;                 // exclusive block offsets
}

__global__ void k_scan3() {
    int i = blockIdx.x * 256 + threadIdx.x;
    if (i < NN) g_off[i] += g_bsum[i >> 8];
    if (i == 0) g_off[NN] = MM;
}

__global__ void k_scatter(const int* __restrict__ node_in,
                          const int* __restrict__ node_out,
                          const int* __restrict__ relation,
                          const float* __restrict__ edge_weight) {
    int m = blockIdx.x * 256 + threadIdx.x;
    if (m >= MM) return;
    int ni, no, r; float ew;
    if (m < EE) {
        ni = node_in[m]; no = node_out[m]; r = relation[m]; ew = edge_weight[m];
    } else {
        ni = no = m - EE; r = RP1 - 1; ew = 1.f;
    }
    int pos = g_off[no] + atomicAdd(&g_cnt2[no], 1);
    uint32_t bi = (uint32_t)r * NN + (uint32_t)ni;   // < 450000, fits 19 bits
    g_erec[pos] = make_uint2(bi | ((uint32_t)r << 24), __float_as_uint(ew));
}

// ---------------------------------------------------------------------------
// Ka: gather-side aggregation, 4 edges per warp-step.
//   lane = jj*8 + dd: jj = edge slot (0..3), dd = head / dim-octet (0..7).
// ---------------------------------------------------------------------------
__global__ __launch_bounds__(256) void k_agg(float* __restrict__ out) {
    const int n = blockIdx.x * 8 + (threadIdx.x >> 5);
    if (n >= NN) return;
    const int lane = threadIdx.x & 31;
    const int jj = lane >> 3, dd = lane & 7;

    const int start = g_off[n];
    const int end   = g_off[n + 1];

    float acc[8];
    #pragma unroll
    for (int k = 0; k < 8; k++) acc[k] = 0.f;
    float esum = 0.f;

    for (int e = start; e < end; e += 4) {
        const int idx = e + jj;
        // pad record (bi=0, r=0, ew=0) -> zero contribution, valid addresses
        uint2 cur = (idx < end) ? g_erec[idx] : make_uint2(0u, 0u);
        const uint32_t bi = cur.x & 0xFFFFFFu;
        const uint32_t r  = cur.x >> 24;

        const uint4 hv = *(const uint4*)(g_hidden + (size_t)bi * 64 + dd * 8);
        const float si = __half2float(g_s[(size_t)bi * 16 + dd]);
        const float so = __half2float(g_s[((size_t)r * NN + n) * 16 + 8 + dd]);

        float w = si + so;
        w = (w > 0.f) ? w : NEG_SLOPE * w;
        const float ee = __expf(w) * __uint_as_float(cur.y);

        const float2 f0 = __half22float2(*(const __half2*)&hv.x);
        const float2 f1 = __half22float2(*(const __half2*)&hv.y);
        const float2 f2 = __half22float2(*(const __half2*)&hv.z);
        const float2 f3 = __half22float2(*(const __half2*)&hv.w);
        acc[0] += ee * f0.x; acc[1] += ee * f0.y;
        acc[2] += ee * f1.x; acc[3] += ee * f1.y;
        acc[4] += ee * f2.x; acc[5] += ee * f2.y;
        acc[6] += ee * f3.x; acc[7] += ee * f3.y;
        esum += ee;
    }

    // fold the 4 edge slots (lanes jj, same dd)
    #pragma unroll
    for (int o = 8; o <= 16; o <<= 1) {
        #pragma unroll
        for (int k = 0; k < 8; k++)
            acc[k] += __shfl_xor_sync(0xffffffffu, acc[k], o);
        esum += __shfl_xor_sync(0xffffffffu, esum, o);
    }

    if (jj == 0) {
        const float inv = 1.f / esum;      // >=1 edge per node (self-loop)
        float4 o0, o1;
        o0.x = fmaxf(acc[0] * inv, 0.f);
        o0.y = fmaxf(acc[1] * inv, 0.f);
        o0.z = fmaxf(acc[2] * inv, 0.f);
        o0.w = fmaxf(acc[3] * inv, 0.f);
        o1.x = fmaxf(acc[4] * inv, 0.f);
        o1.y = fmaxf(acc[5] * inv, 0.f);
        o1.z = fmaxf(acc[6] * inv, 0.f);
        o1.w = fmaxf(acc[7] * inv, 0.f);
        *(float4*)(out + (size_t)n * 64 + dd * 8)     = o0;
        *(float4*)(out + (size_t)n * 64 + dd * 8 + 4) = o1;
    }
}

// ---------------------------------------------------------------------------
extern "C" void kernel_launch(void* const* d_in, const int* in_sizes, int n_in,
                              void* d_out, int out_size) {
    const float* x           = (const float*)d_in[0];
    const float* W_tau       = (const float*)d_in[1];
    const float* query       = (const float*)d_in[2];
    const int*   node_in     = (const int*)  d_in[3];
    const int*   node_out    = (const int*)  d_in[4];
    const int*   relation    = (const int*)  d_in[5];
    const float* edge_weight = (const float*)d_in[6];

    k_zero<<<(NN + 255) / 256, 256>>>();
    k_prepX<<<(G16 * 4 * 32 + 255) / 256, 256>>>(x);
    k_prepWB<<<RP1, 256>>>(W_tau, query);

    // node transform (tensor cores) — 4th launch: captured by ncu
    dim3 gg(MT2, 5);
    k_gemm<<<gg, 128>>>(0);

    // CSR sort by destination
    k_hist<<<(MM + 255) / 256, 256>>>(node_out);
    k_scan1<<<SB1, 256>>>();
    k_scan2<<<1, 256>>>();
    k_scan3<<<SB1, 256>>>();
    k_scatter<<<(MM + 255) / 256, 256>>>(node_in, node_out, relation, edge_weight);

    // gather-side aggregation, fused finalize
    k_agg<<<(NN + 7) / 8, 256>>>((float*)d_out);
}